// round 13
// baseline (speedup 1.0000x reference)
#include <cuda_runtime.h>

#define K_CODES 16384
#define NSAMP   4096
#define DIM     14
#define HW      1024
#define Q_ELEMS 57344            // 4 * 14 * 1024
#define WPB     16               // warps (= samples) per block, kernel A
#define TBLK    16               // blocks, kernel B (16*256 = 4096 threads)

// Module-load zero-initialized; every call restores zeros behind itself so
// each execution (eager correctness run or graph replay) starts identically.
__device__ __align__(16) float g_avg[K_CODES];
__device__ float g_ent_sum;
__device__ float g_hist_sum;
__device__ int   g_done;

__device__ __forceinline__ float warp_sum(float v) {
#pragma unroll
    for (int off = 16; off > 0; off >>= 1)
        v += __shfl_xor_sync(0xffffffffu, v, off);
    return v;
}

// ---------------------------------------------------------------------------
// Kernel A (primary): survivor scatter ONLY — entropy moved to B's pre-wait.
// Fires the PDL trigger AT ENTRY so the dependent kernel starts immediately.
// ONE WARP PER SAMPLE. lane j<14 owns dim j; softmax over +-1 codes
// factorizes per-dim, so the scatter set is: subsets of dims with flip cost
// a_j = 400|xn_j| < 30 (dropped probs < e^-30, below fp32 noise).
// ---------------------------------------------------------------------------
__global__ __launch_bounds__(32 * WPB) void lfq_scatter(const float* __restrict__ x) {
    asm volatile("griddepcontrol.launch_dependents;" ::: "memory");

    __shared__ float sc[WPB][DIM];
    __shared__ int   st[WPB][DIM];

    const int wid  = threadIdx.x >> 5;
    const int lane = threadIdx.x & 31;
    const int s    = blockIdx.x * WPB + wid;    // sample id
    const int b    = s >> 10;
    const int n    = s & (HW - 1);

    float v = 0.0f;
    if (lane < DIM) v = x[(b * DIM + lane) * HW + n];

    const float inv = rsqrtf(warp_sum(v * v));

    const unsigned bal = __ballot_sync(0xffffffffu, v > 0.0f) & 0x3FFFu;
    const int idx = (int)(__brev(bal) >> 18);    // big-endian bit order

    const float a = (lane < DIM) ? 400.0f * fabsf(v) * inv : 1e30f;
    const float logS = warp_sum(__logf(1.0f + __expf(-a)));

    const bool small = (lane < DIM) && (a < 30.0f);
    const unsigned bm = __ballot_sync(0xffffffffu, small);
    const int m = __popc(bm);
    if (small) {
        const int rank = __popc(bm & ((1u << lane) - 1u));
        sc[wid][rank] = a;
        st[wid][rank] = 1 << (13 - lane);
    }
    __syncwarp();

    const float invS = __expf(-logS);
    const int nm = 1 << m;
    for (int mask = lane; mask < nm; mask += 32) {
        float c = 0.0f;
        int tog = 0;
        for (int j = 0; j < m; j++)
            if ((mask >> j) & 1) { c += sc[wid][j]; tog ^= st[wid][j]; }
        if (c < 30.0f)
            atomicAdd(&g_avg[idx ^ tog], __expf(-c) * invS);
    }
    // no block reduce, no trailing sync: block exits as soon as warps finish
}

// ---------------------------------------------------------------------------
// Kernel B (secondary, PDL): starts while A runs.
// PRE-WAIT (A-independent, one sample per thread):
//   q = sign(x) writes + index emit + CLOSED-FORM entropy
//     a_j = 400|xn_j|, logS = sum log(1+e^-a_j), H = logS + sum a_j e_j/(1+e_j)
//   block-reduced, one g_ent_sum atomic per block.
// griddepcontrol.wait  (A complete + memflush -> g_avg visible)
// POST-WAIT: one float4 histogram chunk per thread, MUFU __logf, zero behind
//   itself; last-ticket block (fence+ticket protocol) writes el, resets state.
// ---------------------------------------------------------------------------
__global__ __launch_bounds__(256) void lfq_tail(const float* __restrict__ x,
                                                float* __restrict__ out) {
    __shared__ float wsum[8];
    const int tid  = threadIdx.x;
    const int gtid = blockIdx.x * 256 + tid;     // 0..4095
    const int b    = gtid >> 10;
    const int n    = gtid & (HW - 1);

    // ---- pre-wait: q + index + entropy for sample gtid (overlaps A) ----
    const float* xs = x   + b * DIM * HW + n;
    float*       qo = out + b * DIM * HW + n;

    float v[DIM];
    float ss = 0.0f;
    int idx = 0;
#pragma unroll
    for (int j = 0; j < DIM; j++) {
        v[j] = xs[j * HW];                       // coalesced per j
        ss += v[j] * v[j];
        const bool pos = v[j] > 0.0f;
        qo[j * HW] = pos ? 1.0f : -1.0f;
        if (pos) idx |= (1 << (13 - j));
    }
    out[Q_ELEMS + 1 + gtid] = (float)idx;

    const float inv = rsqrtf(ss);
    float logS = 0.0f, ent2 = 0.0f;
#pragma unroll
    for (int j = 0; j < DIM; j++) {
        const float a = 400.0f * fabsf(v[j]) * inv;
        const float e = __expf(-a);
        logS += __logf(1.0f + e);
        ent2 += __fdividef(a * e, 1.0f + e);
    }
    float ent = logS + ent2;                     // exact per-sample entropy

    ent = warp_sum(ent);
    if ((tid & 31) == 0) wsum[tid >> 5] = ent;
    __syncthreads();
    if (tid < 8) {
        float t = wsum[tid];
#pragma unroll
        for (int off = 4; off > 0; off >>= 1)
            t += __shfl_xor_sync(0xffu, t, off);
        if (tid == 0) atomicAdd(&g_ent_sum, t);
    }

    // ---- wait for primary grid (full completion + memory flush) ----
    asm volatile("griddepcontrol.wait;" ::: "memory");

    // ---- post-wait: histogram fold (one float4 per thread) ----
    const float sN = 1.0f / (float)NSAMP;
    float4 a4 = reinterpret_cast<float4*>(g_avg)[gtid];
    reinterpret_cast<float4*>(g_avg)[gtid] = make_float4(0.f, 0.f, 0.f, 0.f);
    float ms = (a4.x * sN) * __logf(a4.x * sN + 1e-9f)
             + (a4.y * sN) * __logf(a4.y * sN + 1e-9f)
             + (a4.z * sN) * __logf(a4.z * sN + 1e-9f)
             + (a4.w * sN) * __logf(a4.w * sN + 1e-9f);

    ms = warp_sum(ms);
    __syncthreads();                             // wsum reuse safe
    if ((tid & 31) == 0) wsum[tid >> 5] = ms;
    __syncthreads();
    if (tid < 8) {
        float t = wsum[tid];
#pragma unroll
        for (int off = 4; off > 0; off >>= 1)
            t += __shfl_xor_sync(0xffu, t, off);
        if (tid == 0) {
            atomicAdd(&g_hist_sum, t);
            __threadfence();
            const int d = atomicAdd(&g_done, 1);
            if (d == TBLK - 1) {
                // all blocks' ent/hist adds happen-before their ticket adds
                const float hs = *(volatile float*)&g_hist_sum;
                const float es = *(volatile float*)&g_ent_sum;
                // el = entro_mean - mean_entro = es/N + sum a*log(a+eps)
                out[Q_ELEMS] = es * (1.0f / (float)NSAMP) + hs;
                g_hist_sum = 0.0f;
                g_ent_sum  = 0.0f;
                g_done     = 0;
            }
        }
    }
}

extern "C" void kernel_launch(void* const* d_in, const int* in_sizes, int n_in,
                              void* d_out, int out_size) {
    const float* x = (const float*)d_in[0];
    float* out = (float*)d_out;

    lfq_scatter<<<NSAMP / WPB, 32 * WPB>>>(x);

    cudaLaunchConfig_t cfg = {};
    cfg.gridDim  = dim3(TBLK);
    cfg.blockDim = dim3(256);
    cfg.stream   = 0;
    cudaLaunchAttribute attr[1];
    attr[0].id = cudaLaunchAttributeProgrammaticStreamSerialization;
    attr[0].val.programmaticStreamSerializationAllowed = 1;
    cfg.attrs    = attr;
    cfg.numAttrs = 1;
    cudaLaunchKernelEx(&cfg, lfq_tail, x, out);
}